// round 2
// baseline (speedup 1.0000x reference)
#include <cuda_runtime.h>
#include <cstdint>

// Problem constants (fixed by the reference setup_inputs).
#define BROWS 1024
#define CCOLS 100000
#define C4    (CCOLS / 4)        // 25000 float4 per row (100000 % 4 == 0)
#define TSUM  256                // threads per sum block
#define F4PT  4                  // float4 per thread
#define F4PB  (TSUM * F4PT)      // 1024 float4 per block
#define CHUNKS ((C4 + F4PB - 1) / F4PB)  // 25 chunks per row

#define SCALE   64.0f
#define MARGIN  0.35f
#define S_LOG2E 92.33248262743f  // 64 * log2(e)
#define LOG2E   1.4426950408889634f

// Scratch: per-row sum of exp(S*x). Device global (no allocations allowed).
__device__ float g_rowsum[BROWS];

__global__ void loss_init_kernel() {
    int i = blockIdx.x * blockDim.x + threadIdx.x;
    if (i < BROWS) g_rowsum[i] = 0.0f;
}

// One block per (chunk, row). Streams x once, folds exp, reduces, one atomic.
__global__ __launch_bounds__(TSUM) void loss_sum_kernel(const float* __restrict__ x) {
    const int row = blockIdx.y;
    const int base = blockIdx.x * F4PB + threadIdx.x;
    const float4* __restrict__ xr =
        reinterpret_cast<const float4*>(x + (size_t)row * CCOLS);

    float acc = 0.0f;
#pragma unroll
    for (int i = 0; i < F4PT; ++i) {
        int idx = base + i * TSUM;
        if (idx < C4) {
            float4 v = xr[idx];
            acc += exp2f(v.x * S_LOG2E);
            acc += exp2f(v.y * S_LOG2E);
            acc += exp2f(v.z * S_LOG2E);
            acc += exp2f(v.w * S_LOG2E);
        }
    }

    // Warp reduce
#pragma unroll
    for (int o = 16; o > 0; o >>= 1)
        acc += __shfl_xor_sync(0xffffffffu, acc, o);

    __shared__ float smem[TSUM / 32];
    if ((threadIdx.x & 31) == 0) smem[threadIdx.x >> 5] = acc;
    __syncthreads();

    if (threadIdx.x == 0) {
        float s = 0.0f;
#pragma unroll
        for (int w = 0; w < TSUM / 32; ++w) s += smem[w];
        atomicAdd(&g_rowsum[row], s);
    }
}

// One block, 1024 threads: per-row loss + mean.
// NOTE: labels are int32 on device (JAX default x64-disabled downcasts int64).
__global__ __launch_bounds__(BROWS) void loss_final_kernel(
    const float* __restrict__ x,
    const int* __restrict__ label,
    float* __restrict__ out) {
    const int t = threadIdx.x;  // == row

    int lbl = label[t];
    // Defensive clamp: never read out of bounds even if dtype assumption is off.
    if (lbl < 0) lbl = 0;
    if (lbl >= CCOLS) lbl = CCOLS - 1;

    const float xy = x[(size_t)t * CCOLS + lbl];
    const float rsum = g_rowsum[t];

    const float numerator = SCALE * (xy - MARGIN);
    const float exp_num = exp2f(numerator * LOG2E);
    const float exp_sxy = exp2f(xy * S_LOG2E);
    const float denom = exp_num + (rsum - exp_sxy);
    const float L = (numerator - logf(denom)) * (1.0f / SCALE);

    // Block reduce sum of L over 1024 threads.
    float v = L;
#pragma unroll
    for (int o = 16; o > 0; o >>= 1)
        v += __shfl_xor_sync(0xffffffffu, v, o);

    __shared__ float smem[BROWS / 32];  // 32 warp sums
    if ((t & 31) == 0) smem[t >> 5] = v;
    __syncthreads();

    if (t < 32) {
        float s = smem[t];
#pragma unroll
        for (int o = 16; o > 0; o >>= 1)
            s += __shfl_xor_sync(0xffffffffu, s, o);
        if (t == 0) out[0] = -s * (1.0f / (float)BROWS);
    }
}

extern "C" void kernel_launch(void* const* d_in, const int* in_sizes, int n_in,
                              void* d_out, int out_size) {
    const float* x = (const float*)d_in[0];
    const int* label = (const int*)d_in[1];
    float* out = (float*)d_out;

    loss_init_kernel<<<(BROWS + 255) / 256, 256>>>();

    dim3 grid(CHUNKS, BROWS);
    loss_sum_kernel<<<grid, TSUM>>>(x);

    loss_final_kernel<<<1, BROWS>>>(x, label, out);
}

// round 3
// speedup vs baseline: 1.1078x; 1.1078x over previous
#include <cuda_runtime.h>
#include <cstdint>

// Problem constants (fixed by the reference setup_inputs).
#define BROWS 1024
#define CCOLS 100000
#define C4    (CCOLS / 4)        // 25000 float4 per row
#define NTHR  256

#define SCALE   64.0f
#define MARGIN  0.35f
#define S_LOG2E 92.33248262743f  // 64 * log2(e)
#define LOG2E   1.4426950408889634f

// Scratch (device globals: no allocations allowed).
__device__ float g_rowsum[BROWS];
__device__ unsigned int g_count = 0;  // reset to 0 by last block each launch

__global__ __launch_bounds__(NTHR) void loss_fused_kernel(
    const float* __restrict__ x,
    const int* __restrict__ label,
    float* __restrict__ out) {
    const int row = blockIdx.x;
    const int tid = threadIdx.x;
    const float4* __restrict__ xr =
        reinterpret_cast<const float4*>(x + (size_t)row * CCOLS);

    // ---- Phase 1: row sum of exp(S*x) ----
    float acc = 0.0f;
#pragma unroll 4
    for (int idx = tid; idx < C4; idx += NTHR) {
        float4 v = xr[idx];
        acc += exp2f(v.x * S_LOG2E);
        acc += exp2f(v.y * S_LOG2E);
        acc += exp2f(v.z * S_LOG2E);
        acc += exp2f(v.w * S_LOG2E);
    }

#pragma unroll
    for (int o = 16; o > 0; o >>= 1)
        acc += __shfl_xor_sync(0xffffffffu, acc, o);

    __shared__ float smem[NTHR / 32];
    if ((tid & 31) == 0) smem[tid >> 5] = acc;
    __syncthreads();

    __shared__ bool s_last;
    if (tid == 0) {
        float s = 0.0f;
#pragma unroll
        for (int w = 0; w < NTHR / 32; ++w) s += smem[w];
        g_rowsum[row] = s;
        __threadfence();  // make rowsum visible before signaling
        unsigned int prev = atomicAdd(&g_count, 1u);
        s_last = (prev == BROWS - 1);
    }
    __syncthreads();

    // ---- Phase 2: last block computes the final loss ----
    if (!s_last) return;
    __threadfence();  // acquire: see all rows' g_rowsum

    float lsum = 0.0f;
#pragma unroll
    for (int i = 0; i < BROWS / NTHR; ++i) {
        const int r = tid + i * NTHR;
        int lbl = label[r];
        if (lbl < 0) lbl = 0;
        if (lbl >= CCOLS) lbl = CCOLS - 1;

        const float xy = __ldcg(&x[(size_t)r * CCOLS + lbl]);
        const float rsum = *(volatile float*)&g_rowsum[r];

        const float numerator = SCALE * (xy - MARGIN);
        const float exp_num = exp2f(numerator * LOG2E);
        const float exp_sxy = exp2f(xy * S_LOG2E);
        const float denom = exp_num + (rsum - exp_sxy);
        lsum += (numerator - logf(denom)) * (1.0f / SCALE);
    }

#pragma unroll
    for (int o = 16; o > 0; o >>= 1)
        lsum += __shfl_xor_sync(0xffffffffu, lsum, o);

    __shared__ float smem2[NTHR / 32];
    if ((tid & 31) == 0) smem2[tid >> 5] = lsum;
    __syncthreads();

    if (tid == 0) {
        float s = 0.0f;
#pragma unroll
        for (int w = 0; w < NTHR / 32; ++w) s += smem2[w];
        out[0] = -s * (1.0f / (float)BROWS);
        g_count = 0;  // reset for next graph replay (deterministic)
    }
}

extern "C" void kernel_launch(void* const* d_in, const int* in_sizes, int n_in,
                              void* d_out, int out_size) {
    const float* x = (const float*)d_in[0];
    const int* label = (const int*)d_in[1];
    float* out = (float*)d_out;

    loss_fused_kernel<<<BROWS, NTHR>>>(x, label, out);
}

// round 4
// speedup vs baseline: 1.1308x; 1.0208x over previous
#include <cuda_runtime.h>
#include <cstdint>

// Problem constants (fixed by the reference setup_inputs).
#define BROWS 1024
#define CCOLS 100000
#define C4    (CCOLS / 4)        // 25000 float4 per row
#define NTHR  256

#define SCALE   64.0f
#define MARGIN  0.35f
#define S_LOG2E 92.33248262743f  // 64 * log2(e)
#define LOG2E   1.4426950408889634f

// Scratch (device globals: no allocations allowed). Zero at load; the last
// block resets them each launch so graph replays stay correct.
__device__ float g_loss = 0.0f;
__device__ unsigned int g_count = 0;

__global__ __launch_bounds__(NTHR) void loss_fused_kernel(
    const float* __restrict__ x,
    const int* __restrict__ label,
    float* __restrict__ out) {
    const int row = blockIdx.x;
    const int tid = threadIdx.x;
    const float4* __restrict__ xr =
        reinterpret_cast<const float4*>(x + (size_t)row * CCOLS);

    // Issue the target-logit gather early; consumed only at the end, so its
    // latency hides under the full row stream.
    float xy = 0.0f;
    if (tid == 0) {
        int lbl = label[row];
        if (lbl < 0) lbl = 0;
        if (lbl >= CCOLS) lbl = CCOLS - 1;
        xy = x[(size_t)row * CCOLS + lbl];
    }

    // ---- Stream the row, folding exp(S*x). Dual accumulators break the
    // FADD chain so the unrolled LDG.128s batch (higher MLP). ----
    float acc0 = 0.0f, acc1 = 0.0f;
#pragma unroll 4
    for (int idx = tid; idx < C4; idx += NTHR) {
        float4 v = __ldcs(&xr[idx]);
        acc0 += exp2f(v.x * S_LOG2E) + exp2f(v.y * S_LOG2E);
        acc1 += exp2f(v.z * S_LOG2E) + exp2f(v.w * S_LOG2E);
    }
    float acc = acc0 + acc1;

#pragma unroll
    for (int o = 16; o > 0; o >>= 1)
        acc += __shfl_xor_sync(0xffffffffu, acc, o);

    __shared__ float smem[NTHR / 32];
    if ((tid & 31) == 0) smem[tid >> 5] = acc;
    __syncthreads();

    if (tid == 0) {
        float rsum = 0.0f;
#pragma unroll
        for (int w = 0; w < NTHR / 32; ++w) rsum += smem[w];

        // This block's complete loss term.
        const float numerator = SCALE * (xy - MARGIN);
        const float exp_num = exp2f(numerator * LOG2E);
        const float exp_sxy = exp2f(xy * S_LOG2E);
        const float denom = exp_num + (rsum - exp_sxy);
        const float L = (numerator - logf(denom)) * (1.0f / SCALE);

        atomicAdd(&g_loss, L);
        __threadfence();  // order g_loss update before the counter signal
        unsigned int prev = atomicAdd(&g_count, 1u);
        if (prev == BROWS - 1) {
            // Last block: read the full accumulation, emit, reset scratch.
            float total = atomicAdd(&g_loss, 0.0f);
            out[0] = -total * (1.0f / (float)BROWS);
            g_loss = 0.0f;
            __threadfence();
            g_count = 0;
        }
    }
}

extern "C" void kernel_launch(void* const* d_in, const int* in_sizes, int n_in,
                              void* d_out, int out_size) {
    const float* x = (const float*)d_in[0];
    const int* label = (const int*)d_in[1];
    float* out = (float*)d_out;

    loss_fused_kernel<<<BROWS, NTHR>>>(x, label, out);
}